// round 15
// baseline (speedup 1.0000x reference)
#include <cuda_runtime.h>

#define B_TOT 2048
#define H     51
#define HP    52
#define KP    56
#define KU2   14
#define PAIR  120
#define NJG   26
#define WSZ   (NJG*PAIR)
#define E     16
#define TPB   256          // warps 0-6 compute, warp 7 = out + x-prefetch service
#define XCH   40

typedef unsigned long long ull;

struct __align__(16) Smem {
    float l1r[WSZ], l1z[WSZ], l1n[WSZ];
    float ir2[WSZ], iz2[WSZ], in2[WSZ];
    float hr2[WSZ], hz2[WSZ], hn2[WSZ];
    float wih1r[HP], wih1z[HP], wih1n[HP];
    float bR1[HP], bZ1[HP], bIN1[HP], bHN1[HP];
    float bR2[HP], bZ2[HP], bIN2[HP], bHN2[HP];
    float wlin[KP];
    float h1[2][E][KP];
    float h2[2][E][KP];
    float xbuf[2][E][XCH];    // double-buffered, staged by warp 7
    float PO[4][4][8];
    float blin;
};

__device__ __forceinline__ void fma2(ull& d, ull a, ull b) {
    asm("fma.rn.f32x2 %0, %1, %2, %0;" : "+l"(d) : "l"(a), "l"(b));
}
__device__ __forceinline__ ull pack2(float a, float b) {
    ull r; asm("mov.b64 %0, {%1,%2};" : "=l"(r) : "f"(a), "f"(b)); return r;
}
__device__ __forceinline__ float sum2(ull v) {
    float a, b; asm("mov.b64 {%0,%1}, %2;" : "=f"(a), "=f"(b) : "l"(v));
    return a + b;
}
__device__ __forceinline__ float tanha_(float v) {
    float r; asm("tanh.approx.f32 %0, %1;" : "=f"(r) : "f"(v)); return r;
}
__device__ __forceinline__ float sigmoid_(float v) {
    return fmaf(0.5f, tanha_(0.5f * v), 0.5f);
}
__device__ __forceinline__ float gru_cell(float gr, float gz, float gin,
                                          float ghn, float ho) {
    float r = sigmoid_(gr);
    float z = sigmoid_(gz);
    float n = tanha_(fmaf(r, ghn, gin));
    return fmaf(z, ho - n, n);
}
__device__ __forceinline__ float xred(ull a0, ull a1, int kh) {
    ull keep = kh ? a1 : a0;
    ull send = kh ? a0 : a1;
    float sf = sum2(send);
    return sum2(keep) + __shfl_xor_sync(0xFFFFFFFFu, sf, 1);
}

__device__ __forceinline__ void fill_mat(float* dst, const float* src, int g, int tid) {
    for (int idx = tid; idx < WSZ; idx += TPB) {
        int jg = idx / PAIR, rem = idx - jg * PAIR;
        int jj = rem / KP;
        int k  = rem - jj * KP;
        float v = 0.f;
        if (jj < 2) {
            int j = jg * 2 + jj;
            if (j < H && k < H) v = src[(g * H + j) * H + k];
        }
        dst[idx] = v;
    }
}

__device__ __forceinline__ float outdot(Smem* s, const float* hrow) {
    const ulonglong2* hv = (const ulonglong2*)hrow;
    const ulonglong2* wl = (const ulonglong2*)s->wlin;
    ull acc = pack2(s->blin, 0.f);
    #pragma unroll
    for (int k = 0; k < KU2; k++) {
        ulonglong2 h = hv[k], w = wl[k];
        fma2(acc, h.x, w.x); fma2(acc, h.y, w.y);
    }
    return sum2(acc);
}

__device__ __forceinline__ float posum(Smem* s, int eg_, int ei_) {
    const float4* p = (const float4*)&s->PO[eg_][ei_][0];
    float4 a = p[0], b = p[1];
    return s->blin + a.x + a.y + a.z + a.w + b.x + b.y + b.z + b.w;
}

// ---- layer 1 split ----
__device__ __forceinline__ void l1_dot(Smem* s, int rd,
                                       int jg, int j0, int kh, int kb, int eg,
                                       float gr[4], float gz[4], float gn[4])
{
    ull aR[2][4], aZ[2][4], aN[2][4];
    #pragma unroll
    for (int jj = 0; jj < 2; jj++)
        #pragma unroll
        for (int ei = 0; ei < 4; ei++) {
            aR[jj][ei] = (kh == 0) ? pack2(s->bR1[j0 + jj], 0.f) : 0ull;
            aZ[jj][ei] = (kh == 0) ? pack2(s->bZ1[j0 + jj], 0.f) : 0ull;
            aN[jj][ei] = (kh == 0) ? pack2(s->bHN1[j0 + jj], 0.f) : 0ull;
        }
    const ulonglong2* pr = (const ulonglong2*)&s->l1r[jg * PAIR] + kb;
    const ulonglong2* pz = (const ulonglong2*)&s->l1z[jg * PAIR] + kb;
    const ulonglong2* pn = (const ulonglong2*)&s->l1n[jg * PAIR] + kb;
    const ulonglong2* ph = (const ulonglong2*)&s->h1[rd][0][0] + eg * KU2 + kb;
    #pragma unroll
    for (int ki = 0; ki < 7; ki++) {
        ulonglong2 w[6];
        w[0] = pr[ki]; w[1] = pr[ki + KU2];
        w[2] = pz[ki]; w[3] = pz[ki + KU2];
        w[4] = pn[ki]; w[5] = pn[ki + KU2];
        ulonglong2 hv[4];
        #pragma unroll
        for (int ei = 0; ei < 4; ei++) hv[ei] = ph[ki + ei * 4 * KU2];
        #pragma unroll
        for (int jj = 0; jj < 2; jj++)
            #pragma unroll
            for (int ei = 0; ei < 4; ei++) {
                fma2(aR[jj][ei], hv[ei].x, w[0 + jj].x); fma2(aR[jj][ei], hv[ei].y, w[0 + jj].y);
                fma2(aZ[jj][ei], hv[ei].x, w[2 + jj].x); fma2(aZ[jj][ei], hv[ei].y, w[2 + jj].y);
                fma2(aN[jj][ei], hv[ei].x, w[4 + jj].x); fma2(aN[jj][ei], hv[ei].y, w[4 + jj].y);
            }
    }
    #pragma unroll
    for (int ei = 0; ei < 4; ei++) {
        gr[ei] = xred(aR[0][ei], aR[1][ei], kh);
        gz[ei] = xred(aZ[0][ei], aZ[1][ei], kh);
        gn[ei] = xred(aN[0][ei], aN[1][ei], kh);
    }
}

__device__ __forceinline__ void l1_fin(Smem* s, int rd, int wr, const float xv[4],
                                       const float gr[4], const float gz[4],
                                       const float gn[4], int jme, int eg)
{
    const float wr1 = s->wih1r[jme], wz1 = s->wih1z[jme];
    const float wn1 = s->wih1n[jme], bi  = s->bIN1[jme];
    #pragma unroll
    for (int ei = 0; ei < 4; ei++) {
        int el = eg + 4 * ei;
        float ho = s->h1[rd][el][jme];
        float nh = gru_cell(fmaf(xv[ei], wr1, gr[ei]), fmaf(xv[ei], wz1, gz[ei]),
                            fmaf(xv[ei], wn1, bi), gn[ei], ho);
        s->h1[wr][el][jme] = nh;
    }
}

__device__ __forceinline__ void layer1(Smem* s, int rd, int wr, const float xv[4],
                                       int jg, int j0, int jme, int kh, int kb, int eg)
{
    float gr[4], gz[4], gn[4];
    l1_dot(s, rd, jg, j0, kh, kb, eg, gr, gz, gn);
    l1_fin(s, rd, wr, xv, gr, gz, gn, jme, eg);
}

template<bool PO>
__device__ __forceinline__ void layer2(Smem* s, int ub, int vrd, int vwr,
                                       int jg, int j0, int jme, int kh, int kb,
                                       int eg, int lane, int warp, bool clone)
{
    ull aR[2][4], aZ[2][4], aI[2][4], aH[2][4];
    #pragma unroll
    for (int jj = 0; jj < 2; jj++)
        #pragma unroll
        for (int ei = 0; ei < 4; ei++) {
            aR[jj][ei] = (kh == 0) ? pack2(s->bR2[j0 + jj], 0.f) : 0ull;
            aZ[jj][ei] = (kh == 0) ? pack2(s->bZ2[j0 + jj], 0.f) : 0ull;
            aI[jj][ei] = (kh == 0) ? pack2(s->bIN2[j0 + jj], 0.f) : 0ull;
            aH[jj][ei] = (kh == 0) ? pack2(s->bHN2[j0 + jj], 0.f) : 0ull;
        }
    const ulonglong2* pir = (const ulonglong2*)&s->ir2[jg * PAIR] + kb;
    const ulonglong2* piz = (const ulonglong2*)&s->iz2[jg * PAIR] + kb;
    const ulonglong2* pin = (const ulonglong2*)&s->in2[jg * PAIR] + kb;
    const ulonglong2* phr = (const ulonglong2*)&s->hr2[jg * PAIR] + kb;
    const ulonglong2* phz = (const ulonglong2*)&s->hz2[jg * PAIR] + kb;
    const ulonglong2* phn = (const ulonglong2*)&s->hn2[jg * PAIR] + kb;
    const ulonglong2* pu  = (const ulonglong2*)&s->h1[ub][0][0]  + eg * KU2 + kb;
    const ulonglong2* pv  = (const ulonglong2*)&s->h2[vrd][0][0] + eg * KU2 + kb;
    #pragma unroll
    for (int ki = 0; ki < 7; ki++) {
        ulonglong2 wi[6], wh[6];
        wi[0] = pir[ki]; wi[1] = pir[ki + KU2];
        wi[2] = piz[ki]; wi[3] = piz[ki + KU2];
        wi[4] = pin[ki]; wi[5] = pin[ki + KU2];
        wh[0] = phr[ki]; wh[1] = phr[ki + KU2];
        wh[2] = phz[ki]; wh[3] = phz[ki + KU2];
        wh[4] = phn[ki]; wh[5] = phn[ki + KU2];
        ulonglong2 uv[4], vv[4];
        #pragma unroll
        for (int ei = 0; ei < 4; ei++) {
            uv[ei] = pu[ki + ei * 4 * KU2];
            vv[ei] = pv[ki + ei * 4 * KU2];
        }
        #pragma unroll
        for (int jj = 0; jj < 2; jj++)
            #pragma unroll
            for (int ei = 0; ei < 4; ei++) {
                fma2(aR[jj][ei], uv[ei].x, wi[0 + jj].x); fma2(aR[jj][ei], uv[ei].y, wi[0 + jj].y);
                fma2(aR[jj][ei], vv[ei].x, wh[0 + jj].x); fma2(aR[jj][ei], vv[ei].y, wh[0 + jj].y);
                fma2(aZ[jj][ei], uv[ei].x, wi[2 + jj].x); fma2(aZ[jj][ei], uv[ei].y, wi[2 + jj].y);
                fma2(aZ[jj][ei], vv[ei].x, wh[2 + jj].x); fma2(aZ[jj][ei], vv[ei].y, wh[2 + jj].y);
                fma2(aI[jj][ei], uv[ei].x, wi[4 + jj].x); fma2(aI[jj][ei], uv[ei].y, wi[4 + jj].y);
                fma2(aH[jj][ei], vv[ei].x, wh[4 + jj].x); fma2(aH[jj][ei], vv[ei].y, wh[4 + jj].y);
            }
    }
    float gr[4], gz[4], gi[4], gh[4];
    #pragma unroll
    for (int ei = 0; ei < 4; ei++) {
        gr[ei] = xred(aR[0][ei], aR[1][ei], kh);
        gz[ei] = xred(aZ[0][ei], aZ[1][ei], kh);
        gi[ei] = xred(aI[0][ei], aI[1][ei], kh);
        gh[ei] = xred(aH[0][ei], aH[1][ei], kh);
    }
    float nh[4];
    #pragma unroll
    for (int ei = 0; ei < 4; ei++) {
        int el = eg + 4 * ei;
        float ho = s->h2[vrd][el][jme];
        nh[ei] = gru_cell(gr[ei], gz[ei], gi[ei], gh[ei], ho);
        s->h2[vwr][el][jme] = nh[ei];
    }
    if (PO) {
        float wlj = s->wlin[jme];
        float p[4];
        #pragma unroll
        for (int ei = 0; ei < 4; ei++) p[ei] = clone ? 0.f : nh[ei] * wlj;
        #pragma unroll
        for (int ei = 0; ei < 4; ei++) {
            p[ei] += __shfl_xor_sync(0xFFFFFFFFu, p[ei], 1);
            p[ei] += __shfl_xor_sync(0xFFFFFFFFu, p[ei], 8);
            p[ei] += __shfl_xor_sync(0xFFFFFFFFu, p[ei], 16);
        }
        if ((lane & 25) == 0) {
            s->PO[eg][0][warp] = p[0];
            s->PO[eg][1][warp] = p[1];
            s->PO[eg][2][warp] = p[2];
            s->PO[eg][3][warp] = p[3];
        }
    }
}

// warp 7 stages steps i0..i0+XCH-1 into xbuf[BUF] (no barrier; consumed >= 20 intervals later)
#define STAGE_CHUNK(i0, BUF)                                              \
    if (warp == 7) {                                                      \
        for (int k_ = lane; k_ < E * XCH; k_ += 32) {                     \
            int e_ = k_ / XCH, c_ = k_ - e_ * XCH;                        \
            int tg_ = (i0) + c_;                                          \
            s->xbuf[BUF][e_][c_] = (tg_ < T) ? x[(size_t)(base + e_) * T + tg_] : 0.f; \
        }                                                                 \
    }

#define P1_STEP(i, PAR)                                                   \
    {                                                                     \
        if ((i) >= 2 && outw)                                             \
            myout[(i) - 2] = outdot(s, &s->h2[(PAR)][lane][0]);           \
        if (comp) {                                                       \
            const int xidx_ = (i) % XCH;                                  \
            const int xb_   = ((i) / XCH) & 1;                            \
            float xv_[4];                                                 \
            _Pragma("unroll")                                             \
            for (int ei_ = 0; ei_ < 4; ei_++)                             \
                xv_[ei_] = s->xbuf[xb_][eg + 4 * ei_][xidx_];             \
            layer1(s, (PAR) ^ 1, (PAR), xv_, jg, j0, jme, kh, kb, eg);    \
            if ((i) >= 1)                                                 \
                layer2<false>(s, (PAR) ^ 1, (PAR), (PAR) ^ 1,             \
                              jg, j0, jme, kh, kb, eg, lane, warp, clone);\
        }                                                                 \
        __syncthreads();                                                  \
    }

#define BRIDGE(TP)                                                        \
    {                                                                     \
        if (outw) myout[T - 2] = outdot(s, &s->h2[(TP)][lane][0]);        \
        if (comp) {                                                       \
            layer2<true>(s, (TP) ^ 1, (TP), (TP) ^ 1,                     \
                         jg, j0, jme, kh, kb, eg, lane, warp, clone);     \
            l1_dot(s, (TP) ^ 1, jg, j0, kh, kb, eg, g1r, g1z, g1n);       \
        }                                                                 \
        __syncthreads();                                                  \
    }

#define P2_STEP(t, PAR)                                                   \
    {                                                                     \
        if (comp) {                                                       \
            float xv_[4];                                                 \
            _Pragma("unroll")                                             \
            for (int ei_ = 0; ei_ < 4; ei_++)                             \
                xv_[ei_] = posum(s, eg, ei_);                             \
            l1_fin(s, (PAR) ^ 1, (PAR), xv_, g1r, g1z, g1n, jme, eg);     \
        }                                                                 \
        if (outw) myout[(t) - 1] = posum(s, lane & 3, lane >> 2);         \
        __syncthreads();                                                  \
        if (comp) {                                                       \
            layer2<true>(s, (PAR), (PAR) ^ 1, (PAR),                      \
                         jg, j0, jme, kh, kb, eg, lane, warp, clone);     \
            if ((t) + 1 < TF)                                             \
                l1_dot(s, (PAR), jg, j0, kh, kb, eg, g1r, g1z, g1n);      \
        }                                                                 \
        __syncthreads();                                                  \
    }

__global__ void __launch_bounds__(TPB, 1) gru_stack_kernel(
    const float* __restrict__ x,
    const float* __restrict__ w_ih1, const float* __restrict__ w_hh1,
    const float* __restrict__ b_ih1, const float* __restrict__ b_hh1,
    const float* __restrict__ w_ih2, const float* __restrict__ w_hh2,
    const float* __restrict__ b_ih2, const float* __restrict__ b_hh2,
    const float* __restrict__ w_lin, const float* __restrict__ b_lin,
    float* __restrict__ out, int T, int F)
{
    extern __shared__ float smem_f[];
    Smem* s = reinterpret_cast<Smem*>(smem_f);

    const int tid  = threadIdx.x;
    const int kh   = tid & 1;
    const int eg   = (tid >> 1) & 3;
    const int jgr  = tid >> 3;
    const bool comp = (tid < 224);
    const bool clone = comp && (jgr > NJG - 1);
    const int jg   = (jgr > NJG - 1) ? NJG - 1 : jgr;
    const int j0   = 2 * jg;
    const int jme  = j0 + kh;
    const int kb   = kh * (KU2 / 2);
    const int lane = tid & 31;
    const int warp = tid >> 5;
    const int base = blockIdx.x * E;
    const int TF   = T + F;
    const bool outw = (warp == 7) && (lane < 16);
    float* myout = out + (outw ? (size_t)(base + lane) * TF : 0);

    // ---------------- one-time init ----------------
    fill_mat(s->l1r, w_hh1, 0, tid); fill_mat(s->l1z, w_hh1, 1, tid); fill_mat(s->l1n, w_hh1, 2, tid);
    fill_mat(s->ir2, w_ih2, 0, tid); fill_mat(s->iz2, w_ih2, 1, tid); fill_mat(s->in2, w_ih2, 2, tid);
    fill_mat(s->hr2, w_hh2, 0, tid); fill_mat(s->hz2, w_hh2, 1, tid); fill_mat(s->hn2, w_hh2, 2, tid);
    for (int i = tid; i < HP; i += TPB) {
        bool v = (i < H);
        s->wih1r[i] = v ? w_ih1[i] : 0.f;
        s->wih1z[i] = v ? w_ih1[H + i] : 0.f;
        s->wih1n[i] = v ? w_ih1[2 * H + i] : 0.f;
        s->bR1[i]  = v ? (b_ih1[i] + b_hh1[i]) : 0.f;
        s->bZ1[i]  = v ? (b_ih1[H + i] + b_hh1[H + i]) : 0.f;
        s->bIN1[i] = v ? b_ih1[2 * H + i] : 0.f;
        s->bHN1[i] = v ? b_hh1[2 * H + i] : 0.f;
        s->bR2[i]  = v ? (b_ih2[i] + b_hh2[i]) : 0.f;
        s->bZ2[i]  = v ? (b_ih2[H + i] + b_hh2[H + i]) : 0.f;
        s->bIN2[i] = v ? b_ih2[2 * H + i] : 0.f;
        s->bHN2[i] = v ? b_hh2[2 * H + i] : 0.f;
    }
    for (int i = tid; i < KP; i += TPB) s->wlin[i] = (i < H) ? w_lin[i] : 0.f;
    if (tid == 0) s->blin = b_lin[0];
    {
        float* h1f = &s->h1[0][0][0];
        float* h2f = &s->h2[0][0][0];
        for (int i = tid; i < 2 * E * KP; i += TPB) { h1f[i] = 0.f; h2f[i] = 0.f; }
        float* pof = &s->PO[0][0][0];
        for (int i = tid; i < 128; i += TPB) pof[i] = 0.f;
    }
    STAGE_CHUNK(0, 0);        // prestage chunk 0 (covered by the barrier below)
    __syncthreads();

    float g1r[4], g1z[4], g1n[4];

    // ================= phase 1 (teacher forced) =================
    int i = 0;
    for (; i + 1 < T; i += 2) {
        if ((i % XCH) == 20 && i + 20 < T)
            STAGE_CHUNK(i + 20, ((i / XCH) + 1) & 1);
        P1_STEP(i, 0);
        P1_STEP(i + 1, 1);
    }
    if (i < T) {
        if ((i % XCH) == 20 && i + 20 < T)
            STAGE_CHUNK(i + 20, ((i / XCH) + 1) & 1);
        P1_STEP(i, 0);
        i++;
    }

    // bridge
    if ((T & 1) == 0) BRIDGE(0) else BRIDGE(1);

    // ================= phase 2 (autoregressive) =================
    int t = T;
    if (t < TF && (t & 1)) { P2_STEP(t, 1); t++; }
    for (; t + 1 < TF; t += 2) {
        P2_STEP(t, 0);
        P2_STEP(t + 1, 1);
    }
    if (t < TF) { P2_STEP(t, 0); t++; }

    // final output (step TF-1)
    if (outw) myout[TF - 1] = posum(s, lane & 3, lane >> 2);
}

extern "C" void kernel_launch(void* const* d_in, const int* in_sizes, int n_in,
                              void* d_out, int out_size)
{
    const float* x     = (const float*)d_in[0];
    const float* w_ih1 = (const float*)d_in[1];
    const float* w_hh1 = (const float*)d_in[2];
    const float* b_ih1 = (const float*)d_in[3];
    const float* b_hh1 = (const float*)d_in[4];
    const float* w_ih2 = (const float*)d_in[5];
    const float* w_hh2 = (const float*)d_in[6];
    const float* b_ih2 = (const float*)d_in[7];
    const float* b_hh2 = (const float*)d_in[8];
    const float* w_lin = (const float*)d_in[9];
    const float* b_lin = (const float*)d_in[10];

    const int B  = B_TOT;
    const int T  = in_sizes[0] / B;
    const int TF = out_size / B;
    const int F  = TF - T;

    size_t shmem = sizeof(Smem);
    cudaFuncSetAttribute(gru_stack_kernel,
                         cudaFuncAttributeMaxDynamicSharedMemorySize, (int)shmem);

    gru_stack_kernel<<<B / E, TPB, shmem>>>(
        x, w_ih1, w_hh1, b_ih1, b_hh1,
        w_ih2, w_hh2, b_ih2, b_hh2,
        w_lin, b_lin, (float*)d_out, T, F);
}

// round 16
// speedup vs baseline: 1.0200x; 1.0200x over previous
#include <cuda_runtime.h>

#define B_TOT 2048
#define H     51
#define HP    56           // padded gate rows (rows 51..55 = zeros)
#define KP    56
#define KU2   14
#define PAIR  120
#define NJG   28           // row pairs cover rows 0..55; no clone threads
#define WSZ   (NJG*PAIR)
#define E     16
#define TPB   224
#define XCH   40

typedef unsigned long long ull;

struct __align__(16) Smem {
    float l1r[WSZ], l1z[WSZ], l1n[WSZ];
    float ir2[WSZ], iz2[WSZ], in2[WSZ];
    float hr2[WSZ], hz2[WSZ], hn2[WSZ];
    float wih1r[HP], wih1z[HP], wih1n[HP];
    float bR1[HP], bZ1[HP], bIN1[HP], bHN1[HP];
    float bR2[HP], bZ2[HP], bIN2[HP], bHN2[HP];
    float wlin[KP];
    float h1[2][E][KP];
    float h2[2][E][KP];
    float xbuf[E][XCH];
    float PO[4][4][8];
    float blin;
};

__device__ __forceinline__ void fma2(ull& d, ull a, ull b) {
    asm("fma.rn.f32x2 %0, %1, %2, %0;" : "+l"(d) : "l"(a), "l"(b));
}
__device__ __forceinline__ ull pack2(float a, float b) {
    ull r; asm("mov.b64 %0, {%1,%2};" : "=l"(r) : "f"(a), "f"(b)); return r;
}
__device__ __forceinline__ float sum2(ull v) {
    float a, b; asm("mov.b64 {%0,%1}, %2;" : "=f"(a), "=f"(b) : "l"(v));
    return a + b;
}
__device__ __forceinline__ float tanha_(float v) {
    float r; asm("tanh.approx.f32 %0, %1;" : "=f"(r) : "f"(v)); return r;
}
__device__ __forceinline__ float sigmoid_(float v) {
    return fmaf(0.5f, tanha_(0.5f * v), 0.5f);
}
__device__ __forceinline__ float gru_cell(float gr, float gz, float gin,
                                          float ghn, float ho) {
    float r = sigmoid_(gr);
    float z = sigmoid_(gz);
    float n = tanha_(fmaf(r, ghn, gin));
    return fmaf(z, ho - n, n);
}
__device__ __forceinline__ float xred(ull a0, ull a1, int kh) {
    ull keep = kh ? a1 : a0;
    ull send = kh ? a0 : a1;
    float sf = sum2(send);
    return sum2(keep) + __shfl_xor_sync(0xFFFFFFFFu, sf, 1);
}

__device__ __forceinline__ void fill_mat(float* dst, const float* src, int g, int tid) {
    for (int idx = tid; idx < WSZ; idx += TPB) {
        int jg = idx / PAIR, rem = idx - jg * PAIR;
        int jj = rem / KP;
        int k  = rem - jj * KP;
        float v = 0.f;
        if (jj < 2) {
            int j = jg * 2 + jj;
            if (j < H && k < H) v = src[(g * H + j) * H + k];
        }
        dst[idx] = v;
    }
}

__device__ __forceinline__ float outdot(Smem* s, const float* hrow) {
    const ulonglong2* hv = (const ulonglong2*)hrow;
    const ulonglong2* wl = (const ulonglong2*)s->wlin;
    ull acc = pack2(s->blin, 0.f);
    #pragma unroll
    for (int k = 0; k < KU2; k++) {
        ulonglong2 h = hv[k], w = wl[k];
        fma2(acc, h.x, w.x); fma2(acc, h.y, w.y);
    }
    return sum2(acc);
}

__device__ __forceinline__ float posum(Smem* s, int eg_, int ei_) {
    const float4* p = (const float4*)&s->PO[eg_][ei_][0];
    float4 a = p[0], b = p[1];
    return s->blin + a.x + a.y + a.z + a.w + b.x + b.y + b.z + b.w;
}

// ---- layer 1 split ----
__device__ __forceinline__ void l1_dot(Smem* s, int rd,
                                       int jg, int j0, int kh, int kb, int eg,
                                       float gr[4], float gz[4], float gn[4])
{
    ull aR[2][4], aZ[2][4], aN[2][4];
    #pragma unroll
    for (int jj = 0; jj < 2; jj++)
        #pragma unroll
        for (int ei = 0; ei < 4; ei++) {
            aR[jj][ei] = (kh == 0) ? pack2(s->bR1[j0 + jj], 0.f) : 0ull;
            aZ[jj][ei] = (kh == 0) ? pack2(s->bZ1[j0 + jj], 0.f) : 0ull;
            aN[jj][ei] = (kh == 0) ? pack2(s->bHN1[j0 + jj], 0.f) : 0ull;
        }
    const ulonglong2* pr = (const ulonglong2*)&s->l1r[jg * PAIR] + kb;
    const ulonglong2* pz = (const ulonglong2*)&s->l1z[jg * PAIR] + kb;
    const ulonglong2* pn = (const ulonglong2*)&s->l1n[jg * PAIR] + kb;
    const ulonglong2* ph = (const ulonglong2*)&s->h1[rd][0][0] + eg * KU2 + kb;
    #pragma unroll
    for (int ki = 0; ki < 7; ki++) {
        ulonglong2 w[6];
        w[0] = pr[ki]; w[1] = pr[ki + KU2];
        w[2] = pz[ki]; w[3] = pz[ki + KU2];
        w[4] = pn[ki]; w[5] = pn[ki + KU2];
        ulonglong2 hv[4];
        #pragma unroll
        for (int ei = 0; ei < 4; ei++) hv[ei] = ph[ki + ei * 4 * KU2];
        #pragma unroll
        for (int jj = 0; jj < 2; jj++)
            #pragma unroll
            for (int ei = 0; ei < 4; ei++) {
                fma2(aR[jj][ei], hv[ei].x, w[0 + jj].x); fma2(aR[jj][ei], hv[ei].y, w[0 + jj].y);
                fma2(aZ[jj][ei], hv[ei].x, w[2 + jj].x); fma2(aZ[jj][ei], hv[ei].y, w[2 + jj].y);
                fma2(aN[jj][ei], hv[ei].x, w[4 + jj].x); fma2(aN[jj][ei], hv[ei].y, w[4 + jj].y);
            }
    }
    #pragma unroll
    for (int ei = 0; ei < 4; ei++) {
        gr[ei] = xred(aR[0][ei], aR[1][ei], kh);
        gz[ei] = xred(aZ[0][ei], aZ[1][ei], kh);
        gn[ei] = xred(aN[0][ei], aN[1][ei], kh);
    }
}

__device__ __forceinline__ void l1_fin(Smem* s, int rd, int wr, const float xv[4],
                                       const float gr[4], const float gz[4],
                                       const float gn[4], int jme, int eg)
{
    const float wr1 = s->wih1r[jme], wz1 = s->wih1z[jme];
    const float wn1 = s->wih1n[jme], bi  = s->bIN1[jme];
    #pragma unroll
    for (int ei = 0; ei < 4; ei++) {
        int el = eg + 4 * ei;
        float ho = s->h1[rd][el][jme];
        float nh = gru_cell(fmaf(xv[ei], wr1, gr[ei]), fmaf(xv[ei], wz1, gz[ei]),
                            fmaf(xv[ei], wn1, bi), gn[ei], ho);
        s->h1[wr][el][jme] = nh;
    }
}

__device__ __forceinline__ void layer1(Smem* s, int rd, int wr, const float xv[4],
                                       int jg, int j0, int jme, int kh, int kb, int eg)
{
    float gr[4], gz[4], gn[4];
    l1_dot(s, rd, jg, j0, kh, kb, eg, gr, gz, gn);
    l1_fin(s, rd, wr, xv, gr, gz, gn, jme, eg);
}

template<bool PO>
__device__ __forceinline__ void layer2(Smem* s, int ub, int vrd, int vwr,
                                       int jg, int j0, int jme, int kh, int kb,
                                       int eg, int lane, int warp)
{
    ull aR[2][4], aZ[2][4], aI[2][4], aH[2][4];
    #pragma unroll
    for (int jj = 0; jj < 2; jj++)
        #pragma unroll
        for (int ei = 0; ei < 4; ei++) {
            aR[jj][ei] = (kh == 0) ? pack2(s->bR2[j0 + jj], 0.f) : 0ull;
            aZ[jj][ei] = (kh == 0) ? pack2(s->bZ2[j0 + jj], 0.f) : 0ull;
            aI[jj][ei] = (kh == 0) ? pack2(s->bIN2[j0 + jj], 0.f) : 0ull;
            aH[jj][ei] = (kh == 0) ? pack2(s->bHN2[j0 + jj], 0.f) : 0ull;
        }
    const ulonglong2* pir = (const ulonglong2*)&s->ir2[jg * PAIR] + kb;
    const ulonglong2* piz = (const ulonglong2*)&s->iz2[jg * PAIR] + kb;
    const ulonglong2* pin = (const ulonglong2*)&s->in2[jg * PAIR] + kb;
    const ulonglong2* phr = (const ulonglong2*)&s->hr2[jg * PAIR] + kb;
    const ulonglong2* phz = (const ulonglong2*)&s->hz2[jg * PAIR] + kb;
    const ulonglong2* phn = (const ulonglong2*)&s->hn2[jg * PAIR] + kb;
    const ulonglong2* pu  = (const ulonglong2*)&s->h1[ub][0][0]  + eg * KU2 + kb;
    const ulonglong2* pv  = (const ulonglong2*)&s->h2[vrd][0][0] + eg * KU2 + kb;
    #pragma unroll
    for (int ki = 0; ki < 7; ki++) {
        ulonglong2 wi[6], wh[6];
        wi[0] = pir[ki]; wi[1] = pir[ki + KU2];
        wi[2] = piz[ki]; wi[3] = piz[ki + KU2];
        wi[4] = pin[ki]; wi[5] = pin[ki + KU2];
        wh[0] = phr[ki]; wh[1] = phr[ki + KU2];
        wh[2] = phz[ki]; wh[3] = phz[ki + KU2];
        wh[4] = phn[ki]; wh[5] = phn[ki + KU2];
        ulonglong2 uv[4], vv[4];
        #pragma unroll
        for (int ei = 0; ei < 4; ei++) {
            uv[ei] = pu[ki + ei * 4 * KU2];
            vv[ei] = pv[ki + ei * 4 * KU2];
        }
        #pragma unroll
        for (int jj = 0; jj < 2; jj++)
            #pragma unroll
            for (int ei = 0; ei < 4; ei++) {
                fma2(aR[jj][ei], uv[ei].x, wi[0 + jj].x); fma2(aR[jj][ei], uv[ei].y, wi[0 + jj].y);
                fma2(aR[jj][ei], vv[ei].x, wh[0 + jj].x); fma2(aR[jj][ei], vv[ei].y, wh[0 + jj].y);
                fma2(aZ[jj][ei], uv[ei].x, wi[2 + jj].x); fma2(aZ[jj][ei], uv[ei].y, wi[2 + jj].y);
                fma2(aZ[jj][ei], vv[ei].x, wh[2 + jj].x); fma2(aZ[jj][ei], vv[ei].y, wh[2 + jj].y);
                fma2(aI[jj][ei], uv[ei].x, wi[4 + jj].x); fma2(aI[jj][ei], uv[ei].y, wi[4 + jj].y);
                fma2(aH[jj][ei], vv[ei].x, wh[4 + jj].x); fma2(aH[jj][ei], vv[ei].y, wh[4 + jj].y);
            }
    }
    float gr[4], gz[4], gi[4], gh[4];
    #pragma unroll
    for (int ei = 0; ei < 4; ei++) {
        gr[ei] = xred(aR[0][ei], aR[1][ei], kh);
        gz[ei] = xred(aZ[0][ei], aZ[1][ei], kh);
        gi[ei] = xred(aI[0][ei], aI[1][ei], kh);
        gh[ei] = xred(aH[0][ei], aH[1][ei], kh);
    }
    float nh[4];
    #pragma unroll
    for (int ei = 0; ei < 4; ei++) {
        int el = eg + 4 * ei;
        float ho = s->h2[vrd][el][jme];
        nh[ei] = gru_cell(gr[ei], gz[ei], gi[ei], gh[ei], ho);
        s->h2[vwr][el][jme] = nh[ei];
    }
    if (PO) {
        // rows 52..55 contribute 0 naturally: wlin[52..55] = 0
        float wlj = s->wlin[jme];
        float p[4];
        #pragma unroll
        for (int ei = 0; ei < 4; ei++) p[ei] = nh[ei] * wlj;
        #pragma unroll
        for (int ei = 0; ei < 4; ei++) {
            p[ei] += __shfl_xor_sync(0xFFFFFFFFu, p[ei], 1);
            p[ei] += __shfl_xor_sync(0xFFFFFFFFu, p[ei], 8);
            p[ei] += __shfl_xor_sync(0xFFFFFFFFu, p[ei], 16);
        }
        if ((lane & 25) == 0) {
            s->PO[eg][0][warp] = p[0];
            s->PO[eg][1][warp] = p[1];
            s->PO[eg][2][warp] = p[2];
            s->PO[eg][3][warp] = p[3];
        }
    }
}

// ---- compile-time-parity step bodies ----
#define STAGE_X(i)                                                        \
    {                                                                     \
        for (int k_ = tid; k_ < E * XCH; k_ += TPB) {                     \
            int e_ = k_ / XCH, c_ = k_ - e_ * XCH;                        \
            int tg_ = (i) + c_;                                           \
            s->xbuf[e_][c_] = (tg_ < T) ? x[(size_t)(base + e_) * T + tg_] : 0.f; \
        }                                                                 \
        __syncthreads();                                                  \
    }

#define P1_STEP(i, PAR)                                                   \
    {                                                                     \
        const int xidx_ = (i) % XCH;                                      \
        if ((i) >= 2 && outw)                                             \
            myout[(i) - 2] = outdot(s, &s->h2[(PAR)][lane][0]);           \
        float xv_[4];                                                     \
        _Pragma("unroll")                                                 \
        for (int ei_ = 0; ei_ < 4; ei_++)                                 \
            xv_[ei_] = s->xbuf[eg + 4 * ei_][xidx_];                      \
        layer1(s, (PAR) ^ 1, (PAR), xv_, jg, j0, jme, kh, kb, eg);        \
        if ((i) >= 1)                                                     \
            layer2<false>(s, (PAR) ^ 1, (PAR), (PAR) ^ 1,                 \
                          jg, j0, jme, kh, kb, eg, lane, warp);           \
        __syncthreads();                                                  \
    }

#define BRIDGE(TP)                                                        \
    {                                                                     \
        if (outw) myout[T - 2] = outdot(s, &s->h2[(TP)][lane][0]);        \
        layer2<true>(s, (TP) ^ 1, (TP), (TP) ^ 1,                         \
                     jg, j0, jme, kh, kb, eg, lane, warp);                \
        l1_dot(s, (TP) ^ 1, jg, j0, kh, kb, eg, g1r, g1z, g1n);           \
        __syncthreads();                                                  \
    }

#define P2_STEP(t, PAR)                                                   \
    {                                                                     \
        float xv_[4];                                                     \
        _Pragma("unroll")                                                 \
        for (int ei_ = 0; ei_ < 4; ei_++)                                 \
            xv_[ei_] = posum(s, eg, ei_);                                 \
        l1_fin(s, (PAR) ^ 1, (PAR), xv_, g1r, g1z, g1n, jme, eg);         \
        if (outw) myout[(t) - 1] = posum(s, lane & 3, lane >> 2);         \
        __syncthreads();                                                  \
        layer2<true>(s, (PAR), (PAR) ^ 1, (PAR),                          \
                     jg, j0, jme, kh, kb, eg, lane, warp);                \
        if ((t) + 1 < TF)                                                 \
            l1_dot(s, (PAR), jg, j0, kh, kb, eg, g1r, g1z, g1n);          \
        __syncthreads();                                                  \
    }

__global__ void __launch_bounds__(TPB, 1) gru_stack_kernel(
    const float* __restrict__ x,
    const float* __restrict__ w_ih1, const float* __restrict__ w_hh1,
    const float* __restrict__ b_ih1, const float* __restrict__ b_hh1,
    const float* __restrict__ w_ih2, const float* __restrict__ w_hh2,
    const float* __restrict__ b_ih2, const float* __restrict__ b_hh2,
    const float* __restrict__ w_lin, const float* __restrict__ b_lin,
    float* __restrict__ out, int T, int F)
{
    extern __shared__ float smem_f[];
    Smem* s = reinterpret_cast<Smem*>(smem_f);

    const int tid  = threadIdx.x;
    const int kh   = tid & 1;
    const int eg   = (tid >> 1) & 3;
    const int jg   = tid >> 3;              // 0..27, all real (rows 52..55 zero)
    const int j0   = 2 * jg;
    const int jme  = j0 + kh;
    const int kb   = kh * (KU2 / 2);
    const int lane = tid & 31;
    const int warp = tid >> 5;
    const int base = blockIdx.x * E;
    const int TF   = T + F;
    const bool outw = (warp == 3) && (lane < 16);
    float* myout = out + (outw ? (size_t)(base + lane) * TF : 0);

    // ---------------- one-time init ----------------
    fill_mat(s->l1r, w_hh1, 0, tid); fill_mat(s->l1z, w_hh1, 1, tid); fill_mat(s->l1n, w_hh1, 2, tid);
    fill_mat(s->ir2, w_ih2, 0, tid); fill_mat(s->iz2, w_ih2, 1, tid); fill_mat(s->in2, w_ih2, 2, tid);
    fill_mat(s->hr2, w_hh2, 0, tid); fill_mat(s->hz2, w_hh2, 1, tid); fill_mat(s->hn2, w_hh2, 2, tid);
    for (int i = tid; i < HP; i += TPB) {
        bool v = (i < H);
        s->wih1r[i] = v ? w_ih1[i] : 0.f;
        s->wih1z[i] = v ? w_ih1[H + i] : 0.f;
        s->wih1n[i] = v ? w_ih1[2 * H + i] : 0.f;
        s->bR1[i]  = v ? (b_ih1[i] + b_hh1[i]) : 0.f;
        s->bZ1[i]  = v ? (b_ih1[H + i] + b_hh1[H + i]) : 0.f;
        s->bIN1[i] = v ? b_ih1[2 * H + i] : 0.f;
        s->bHN1[i] = v ? b_hh1[2 * H + i] : 0.f;
        s->bR2[i]  = v ? (b_ih2[i] + b_hh2[i]) : 0.f;
        s->bZ2[i]  = v ? (b_ih2[H + i] + b_hh2[H + i]) : 0.f;
        s->bIN2[i] = v ? b_ih2[2 * H + i] : 0.f;
        s->bHN2[i] = v ? b_hh2[2 * H + i] : 0.f;
    }
    for (int i = tid; i < KP; i += TPB) s->wlin[i] = (i < H) ? w_lin[i] : 0.f;
    if (tid == 0) s->blin = b_lin[0];
    {
        float* h1f = &s->h1[0][0][0];
        float* h2f = &s->h2[0][0][0];
        for (int i = tid; i < 2 * E * KP; i += TPB) { h1f[i] = 0.f; h2f[i] = 0.f; }
        float* pof = &s->PO[0][0][0];
        for (int i = tid; i < 128; i += TPB) pof[i] = 0.f;
    }
    __syncthreads();

    float g1r[4], g1z[4], g1n[4];

    // ================= phase 1 (teacher forced) =================
    int i = 0;
    for (; i + 1 < T; i += 2) {
        if ((i % XCH) == 0) STAGE_X(i);
        P1_STEP(i, 0);
        P1_STEP(i + 1, 1);
    }
    if (i < T) {
        if ((i % XCH) == 0) STAGE_X(i);
        P1_STEP(i, 0);
        i++;
    }

    // bridge
    if ((T & 1) == 0) BRIDGE(0) else BRIDGE(1);

    // ================= phase 2 (autoregressive) =================
    int t = T;
    if (t < TF && (t & 1)) { P2_STEP(t, 1); t++; }
    for (; t + 1 < TF; t += 2) {
        P2_STEP(t, 0);
        P2_STEP(t + 1, 1);
    }
    if (t < TF) { P2_STEP(t, 0); t++; }

    // final output (step TF-1)
    if (outw) myout[TF - 1] = posum(s, lane & 3, lane >> 2);
}

extern "C" void kernel_launch(void* const* d_in, const int* in_sizes, int n_in,
                              void* d_out, int out_size)
{
    const float* x     = (const float*)d_in[0];
    const float* w_ih1 = (const float*)d_in[1];
    const float* w_hh1 = (const float*)d_in[2];
    const float* b_ih1 = (const float*)d_in[3];
    const float* b_hh1 = (const float*)d_in[4];
    const float* w_ih2 = (const float*)d_in[5];
    const float* w_hh2 = (const float*)d_in[6];
    const float* b_ih2 = (const float*)d_in[7];
    const float* b_hh2 = (const float*)d_in[8];
    const float* w_lin = (const float*)d_in[9];
    const float* b_lin = (const float*)d_in[10];

    const int B  = B_TOT;
    const int T  = in_sizes[0] / B;
    const int TF = out_size / B;
    const int F  = TF - T;

    size_t shmem = sizeof(Smem);
    cudaFuncSetAttribute(gru_stack_kernel,
                         cudaFuncAttributeMaxDynamicSharedMemorySize, (int)shmem);

    gru_stack_kernel<<<B / E, TPB, shmem>>>(
        x, w_ih1, w_hh1, b_ih1, b_hh1,
        w_ih2, w_hh2, b_ih2, b_hh2,
        w_lin, b_lin, (float*)d_out, T, F);
}